// round 3
// baseline (speedup 1.0000x reference)
#include <cuda_runtime.h>

#define BB 4
#define SS 256
#define HH 128
#define NR 40
#define TI 8
#define NT 1024

// 2*log2(e): exp(2x) = 2^(C*x)
#define CEXP 2.8853900817779268f

// shared layout (float words)
#define O_QW   0            // 5120: C*qw   (phase C: vw, unscaled)
#define O_KW   5120         // 5120: C*kw
#define O_REL  10240        // 5120: 2*rel
#define O_Q    15360        // 32768: query[b]  (phase C: value[b])
#define O_E12  48128        // 8*256 int2 (e1=rel_idx[b,j,i], e2=rel_idx[b,i,j])
                            // (phase C: 1024 float2 partials overlay)
#define O_P    52224        // 8*256 float2 (score->a*inv, e1 bits)
#define O_SUMR 56320        // 40 (+pad)
#define SMEM_FLOATS 56384
#define SMEM_BYTES  (SMEM_FLOATS * 4)

__device__ __forceinline__ float ex2(float y) {
    float r; asm("ex2.approx.f32 %0, %1;" : "=f"(r) : "f"(y)); return r;
}
__device__ __forceinline__ float rcp(float d) {
    float r; asm("rcp.approx.f32 %0, %1;" : "=f"(r) : "f"(d)); return r;
}

__global__ void __launch_bounds__(NT, 1)
rgat_kernel(const float* __restrict__ query, const float* __restrict__ key,
            const float* __restrict__ value, const float* __restrict__ rel_emb,
            const float* __restrict__ qw_emb, const float* __restrict__ kw_emb,
            const float* __restrict__ vw_emb, const int* __restrict__ src_len,
            const int* __restrict__ rel_idx, float* __restrict__ out)
{
    extern __shared__ float sm[];
    float*  sh_qw   = sm + O_QW;
    float*  sh_kw   = sm + O_KW;
    float*  sh_rel  = sm + O_REL;
    float*  sh_q    = sm + O_Q;
    int2*   sh_e12  = (int2*)(sm + O_E12);
    float2* sh_p2   = (float2*)(sm + O_P);
    float*  sh_sumR = sm + O_SUMR;

    const int tid = threadIdx.x;
    const int b  = blockIdx.x / (SS / TI);
    const int i0 = (blockIdx.x % (SS / TI)) * TI;
    const int srclen = src_len[b];

    const int TBL = NR * HH; // 5120

    // ---- stage tables with folded constants ----
    for (int k = tid * 4; k < TBL; k += NT * 4) {
        float4 a = *(const float4*)(qw_emb + k);
        a.x *= CEXP; a.y *= CEXP; a.z *= CEXP; a.w *= CEXP;
        *(float4*)(sh_qw + k) = a;
        float4 c = *(const float4*)(kw_emb + k);
        c.x *= CEXP; c.y *= CEXP; c.z *= CEXP; c.w *= CEXP;
        *(float4*)(sh_kw + k) = c;
        float4 r = *(const float4*)(rel_emb + k);
        r.x += r.x; r.y += r.y; r.z += r.z; r.w += r.w;
        *(float4*)(sh_rel + k) = r;
    }
    // ---- sumR[e] = sum_h rel_emb[e,h] (unscaled) ----
    if (tid < NR) {
        const float4* rp = (const float4*)(rel_emb + tid * HH);
        float s = 0.0f;
        #pragma unroll
        for (int c = 0; c < HH / 4; c++) {
            float4 r = rp[c];
            s += (r.x + r.y) + (r.z + r.w);
        }
        sh_sumR[tid] = s;
    }
    // ---- stage full query[b] ----
    const float* qb = query + b * SS * HH;
    for (int k = tid * 4; k < SS * HH; k += NT * 4)
        *(float4*)(sh_q + k) = *(const float4*)(qb + k);

    // ---- stage e12: .x = e1 = rel_idx[b,j,i0+ii] (transpose), .y = e2 = rel_idx[b,i0+ii,j] ----
    if (tid < 512) {
        int j = tid >> 1;
        int c = (tid & 1) * 4;
        int4 v = *(const int4*)(rel_idx + ((size_t)b * SS + j) * SS + i0 + c);
        sh_e12[(c + 0) * SS + j].x = v.x;
        sh_e12[(c + 1) * SS + j].x = v.y;
        sh_e12[(c + 2) * SS + j].x = v.z;
        sh_e12[(c + 3) * SS + j].x = v.w;

        int ii = tid >> 6;
        int j4 = (tid & 63) * 4;
        int4 u = *(const int4*)(rel_idx + ((size_t)b * SS + i0 + ii) * SS + j4);
        sh_e12[ii * SS + j4 + 0].y = u.x;
        sh_e12[ii * SS + j4 + 1].y = u.y;
        sh_e12[ii * SS + j4 + 2].y = u.z;
        sh_e12[ii * SS + j4 + 3].y = u.w;
    }
    __syncthreads();

    const int w    = tid >> 5;
    const int lane = tid & 31;

    // ================= Phase A: scores =================
    // warp -> (row iw = w>>2, j offset p = w&3); 8-lane groups each own one j.
    // score = sumR[e1] - sum_h (2*rel)[e1,h] * rcp(1 + 2^(C*(qw*q + kw*k)))
    {
        const int iw  = w >> 2;
        const int p   = w & 3;
        const int g   = lane >> 3;
        const int lig = lane & 7;

        const float* kb = key + ((size_t)b * SS + i0 + iw) * HH + lig * 4;
        const float4 kr0 = *(const float4*)(kb + 0);
        const float4 kr1 = *(const float4*)(kb + 32);
        const float4 kr2 = *(const float4*)(kb + 64);
        const float4 kr3 = *(const float4*)(kb + 96);

        #pragma unroll 2
        for (int jj = 0; jj < 16; jj++) {
            const int jb = p + (jj << 4);      // warp-uniform
            const int j  = jb + (g << 2);
            if (jb >= srclen) {
                if (lig == 0) sh_p2[iw * SS + j] = make_float2(-1e18f, 0.0f);
                continue;
            }
            const int2 e = sh_e12[iw * SS + j];          // broadcast in group
            const float* qp  = sh_q   + j   * HH + lig * 4;
            const float* qwp = sh_qw  + e.x * HH + lig * 4;
            const float* kwp = sh_kw  + e.y * HH + lig * 4;
            const float* rp  = sh_rel + e.x * HH + lig * 4;

            float a0 = 0.0f, a1 = 0.0f, a2 = 0.0f, a3 = 0.0f;
#define ASTEP(KR, OFF, ACC) { \
            const float4 q  = *(const float4*)(qp  + OFF); \
            const float4 qw = *(const float4*)(qwp + OFF); \
            const float4 kw = *(const float4*)(kwp + OFF); \
            const float4 r  = *(const float4*)(rp  + OFF); \
            ACC = fmaf(r.x, rcp(1.0f + ex2(fmaf(qw.x, q.x, kw.x * KR.x))), ACC); \
            ACC = fmaf(r.y, rcp(1.0f + ex2(fmaf(qw.y, q.y, kw.y * KR.y))), ACC); \
            ACC = fmaf(r.z, rcp(1.0f + ex2(fmaf(qw.z, q.z, kw.z * KR.z))), ACC); \
            ACC = fmaf(r.w, rcp(1.0f + ex2(fmaf(qw.w, q.w, kw.w * KR.w))), ACC); }
            ASTEP(kr0,  0, a0)
            ASTEP(kr1, 32, a1)
            ASTEP(kr2, 64, a2)
            ASTEP(kr3, 96, a3)
#undef ASTEP
            float acc = (a0 + a1) + (a2 + a3);
            acc += __shfl_xor_sync(0xffffffffu, acc, 4);
            acc += __shfl_xor_sync(0xffffffffu, acc, 2);
            acc += __shfl_xor_sync(0xffffffffu, acc, 1);
            if (lig == 0) {
                float sv = (j < srclen) ? (sh_sumR[e.x] - acc) : -1e18f;
                sh_p2[iw * SS + j] = make_float2(sv, __int_as_float(e.x));
            }
        }
    }
    __syncthreads();

    // ---- restage value[b] over sh_q, vw table (unscaled) over sh_qw ----
    const float* vb = value + b * SS * HH;
    for (int k = tid * 4; k < SS * HH; k += NT * 4)
        *(float4*)(sh_q + k) = *(const float4*)(vb + k);
    for (int k = tid * 4; k < TBL; k += NT * 4)
        *(float4*)(sh_qw + k) = *(const float4*)(vw_emb + k);

    // ================= Phase B: softmax, pre-normalized (warps 0..7) =========
    if (w < TI) {
        float2 vals[8];
        float m = -3.0e38f;
        #pragma unroll
        for (int k = 0; k < 8; k++) {
            vals[k] = sh_p2[w * SS + lane + k * 32];
            m = fmaxf(m, vals[k].x);
        }
        #pragma unroll
        for (int o = 16; o; o >>= 1) m = fmaxf(m, __shfl_xor_sync(0xffffffffu, m, o));
        float ssum = 0.0f;
        #pragma unroll
        for (int k = 0; k < 8; k++) {
            float e = __expf(vals[k].x - m);   // masked -> 0
            vals[k].x = e;
            ssum += e;
        }
        #pragma unroll
        for (int o = 16; o; o >>= 1) ssum += __shfl_xor_sync(0xffffffffu, ssum, o);
        const float inv = 1.0f / ssum;
        #pragma unroll
        for (int k = 0; k < 8; k++)
            sh_p2[w * SS + lane + k * 32] = make_float2(vals[k].x * inv, vals[k].y);
    }
    __syncthreads();

    // ================= Phase C: output =================
    // thread -> (row ci, j parity jp, float2 h). (a,e1) is one warp-uniform
    // broadcast; vw/value LDS.64 conflict-free.
    float2* part2 = (float2*)(sm + O_E12);   // overlay (e12 dead)
    {
        const int ci = tid >> 7;              // 0..7
        const int sub = tid & 127;
        const int jp = sub >> 6;              // 0..1 (warp-uniform)
        const int hq = sub & 63;
        const float2* prow = sh_p2 + ci * SS;
        const float* vwb = sh_qw + hq * 2;
        const float* vvb = sh_q  + hq * 2;
        float2 acc = make_float2(0.0f, 0.0f);
        #pragma unroll 4
        for (int j = jp; j < srclen; j += 2) {
            const float2 pe = prow[j];
            const int e1 = __float_as_int(pe.y);
            const float2 vw = *(const float2*)(vwb + e1 * HH);
            const float2 vv = *(const float2*)(vvb + j  * HH);
            acc.x = fmaf(pe.x * vw.x, vv.x, acc.x);
            acc.y = fmaf(pe.x * vw.y, vv.y, acc.y);
        }
        part2[tid] = acc;
    }
    __syncthreads();
    if (tid < 512) {
        const int ci = tid >> 6;
        const int hq = tid & 63;
        const float2 r0 = part2[ci * 128 + hq];
        const float2 r1 = part2[ci * 128 + 64 + hq];
        float2 o = make_float2(r0.x + r1.x, r0.y + r1.y);
        *(float2*)(out + ((size_t)b * SS + i0 + ci) * HH + hq * 2) = o;
    }
}

extern "C" void kernel_launch(void* const* d_in, const int* in_sizes, int n_in,
                              void* d_out, int out_size) {
    const float* query   = (const float*)d_in[0];
    const float* key_t   = (const float*)d_in[1];
    const float* value   = (const float*)d_in[2];
    const float* rel_emb = (const float*)d_in[3];
    const float* qw_emb  = (const float*)d_in[4];
    const float* kw_emb  = (const float*)d_in[5];
    const float* vw_emb  = (const float*)d_in[6];
    const int*   src_len = (const int*)d_in[7];
    const int*   rel_idx = (const int*)d_in[8];
    float* out = (float*)d_out;

    cudaFuncSetAttribute(rgat_kernel,
                         cudaFuncAttributeMaxDynamicSharedMemorySize, SMEM_BYTES);

    rgat_kernel<<<BB * (SS / TI), NT, SMEM_BYTES>>>(
        query, key_t, value, rel_emb, qw_emb, kw_emb, vw_emb,
        src_len, rel_idx, out);
}

// round 7
// speedup vs baseline: 1.0814x; 1.0814x over previous
#include <cuda_runtime.h>

#define BB 4
#define SS 256
#define HH 128
#define NR 40
#define TI 8
#define NT 1024

// shared layout (float words)
#define O_QW   0            // 5120 qw   (phase C: vw)
#define O_KW   5120         // 5120 kw
#define O_REL  10240        // 5120 rel
#define O_Q    15360        // 32768 query[b]  (phase C: value[b])
#define O_E12  48128        // 8*256 int2 (e1, e2)  (phase C: partials overlay)
#define O_P    52224        // 8*256 float2 (a*inv, e1 bits)
#define SMEM_FLOATS 56320
#define SMEM_BYTES  (SMEM_FLOATS * 4)

typedef unsigned long long ull;

__device__ __forceinline__ ull mul2(ull a, ull b) {
    ull d; asm("mul.rn.f32x2 %0, %1, %2;" : "=l"(d) : "l"(a), "l"(b)); return d;
}
__device__ __forceinline__ ull fma2(ull a, ull b, ull c) {
    ull d; asm("fma.rn.f32x2 %0, %1, %2, %3;" : "=l"(d) : "l"(a), "l"(b), "l"(c)); return d;
}
__device__ __forceinline__ ull add2(ull a, ull b) {
    ull d; asm("add.rn.f32x2 %0, %1, %2;" : "=l"(d) : "l"(a), "l"(b)); return d;
}
__device__ __forceinline__ void upk(ull v, float& lo, float& hi) {
    asm("mov.b64 {%0, %1}, %2;" : "=f"(lo), "=f"(hi) : "l"(v));
}
__device__ __forceinline__ ull pk(float lo, float hi) {
    ull r; asm("mov.b64 %0, {%1, %2};" : "=l"(r) : "f"(lo), "f"(hi)); return r;
}
__device__ __forceinline__ float tanhap(float x) {
    float r; asm("tanh.approx.f32 %0, %1;" : "=f"(r) : "f"(x)); return r;
}
// packed tanh: unpack, 2x MUFU.TANH, repack
__device__ __forceinline__ ull tanh2(ull x) {
    float lo, hi; upk(x, lo, hi);
    return pk(tanhap(lo), tanhap(hi));
}

__global__ void __launch_bounds__(NT, 1)
rgat_kernel(const float* __restrict__ query, const float* __restrict__ key,
            const float* __restrict__ value, const float* __restrict__ rel_emb,
            const float* __restrict__ qw_emb, const float* __restrict__ kw_emb,
            const float* __restrict__ vw_emb, const int* __restrict__ src_len,
            const int* __restrict__ rel_idx, float* __restrict__ out)
{
    extern __shared__ float sm[];
    float*  sh_qw  = sm + O_QW;
    float*  sh_kw  = sm + O_KW;
    float*  sh_rel = sm + O_REL;
    float*  sh_q   = sm + O_Q;
    int2*   sh_e12 = (int2*)(sm + O_E12);
    float2* sh_p2  = (float2*)(sm + O_P);

    const int tid = threadIdx.x;
    const int b  = blockIdx.x / (SS / TI);
    const int i0 = (blockIdx.x % (SS / TI)) * TI;
    const int srclen = src_len[b];

    const int TBL = NR * HH; // 5120

    // ---- stage tables ----
    for (int k = tid * 4; k < TBL; k += NT * 4) {
        *(float4*)(sh_qw  + k) = *(const float4*)(qw_emb  + k);
        *(float4*)(sh_kw  + k) = *(const float4*)(kw_emb  + k);
        *(float4*)(sh_rel + k) = *(const float4*)(rel_emb + k);
    }
    // ---- stage full query[b] ----
    const float* qb = query + b * SS * HH;
    for (int k = tid * 4; k < SS * HH; k += NT * 4)
        *(float4*)(sh_q + k) = *(const float4*)(qb + k);

    // ---- stage e12: .x = e1 = rel_idx[b,j,i0+ii] (transpose), .y = e2 = rel_idx[b,i0+ii,j] ----
    if (tid < 512) {
        int j = tid >> 1;
        int c = (tid & 1) * 4;
        int4 v = *(const int4*)(rel_idx + ((size_t)b * SS + j) * SS + i0 + c);
        sh_e12[(c + 0) * SS + j].x = v.x;
        sh_e12[(c + 1) * SS + j].x = v.y;
        sh_e12[(c + 2) * SS + j].x = v.z;
        sh_e12[(c + 3) * SS + j].x = v.w;

        int ii = tid >> 6;
        int j4 = (tid & 63) * 4;
        int4 u = *(const int4*)(rel_idx + ((size_t)b * SS + i0 + ii) * SS + j4);
        sh_e12[ii * SS + j4 + 0].y = u.x;
        sh_e12[ii * SS + j4 + 1].y = u.y;
        sh_e12[ii * SS + j4 + 2].y = u.z;
        sh_e12[ii * SS + j4 + 3].y = u.w;
    }
    __syncthreads();

    const int w    = tid >> 5;
    const int lane = tid & 31;

    // ================= Phase A: scores =================
    // warp -> (row iw = w>>2, j offset p = w&3); four 8-lane groups each own
    // one j; lane covers 16 h (8x packed f32x2 lanes).
    {
        const int iw  = w >> 2;
        const int p   = w & 3;
        const int g   = lane >> 3;
        const int lig = lane & 7;

        const float* kb = key + ((size_t)b * SS + i0 + iw) * HH + lig * 4;
        const ulonglong2 kr0 = *(const ulonglong2*)(kb + 0);
        const ulonglong2 kr1 = *(const ulonglong2*)(kb + 32);
        const ulonglong2 kr2 = *(const ulonglong2*)(kb + 64);
        const ulonglong2 kr3 = *(const ulonglong2*)(kb + 96);

        #pragma unroll 2
        for (int jj = 0; jj < 16; jj++) {
            const int jb = p + (jj << 4);      // warp-uniform
            const int j  = jb + (g << 2);
            if (jb >= srclen) {
                if (lig == 0) sh_p2[iw * SS + j] = make_float2(-1e18f, 0.0f);
                continue;
            }
            const int2 e = sh_e12[iw * SS + j];          // broadcast in group
            const float* qp  = sh_q   + j   * HH + lig * 4;
            const float* qwp = sh_qw  + e.x * HH + lig * 4;
            const float* kwp = sh_kw  + e.y * HH + lig * 4;
            const float* rp  = sh_rel + e.x * HH + lig * 4;

            ull a0 = 0, a1 = 0, a2 = 0, a3 = 0;
#define ASTEP(KR, OFF, ACC) { \
            const ulonglong2 q  = *(const ulonglong2*)(qp  + OFF); \
            const ulonglong2 qw = *(const ulonglong2*)(qwp + OFF); \
            const ulonglong2 kw = *(const ulonglong2*)(kwp + OFF); \
            const ulonglong2 r  = *(const ulonglong2*)(rp  + OFF); \
            ACC = fma2(r.x, tanh2(fma2(qw.x, q.x, mul2(kw.x, KR.x))), ACC); \
            ACC = fma2(r.y, tanh2(fma2(qw.y, q.y, mul2(kw.y, KR.y))), ACC); }
            ASTEP(kr0,  0, a0)
            ASTEP(kr1, 32, a1)
            ASTEP(kr2, 64, a2)
            ASTEP(kr3, 96, a3)
#undef ASTEP
            ull s2 = add2(add2(a0, a1), add2(a2, a3));
            float slo, shi; upk(s2, slo, shi);
            float acc = slo + shi;
            // 8-lane group butterfly (xor offsets stay within the group)
            acc += __shfl_xor_sync(0xffffffffu, acc, 4);
            acc += __shfl_xor_sync(0xffffffffu, acc, 2);
            acc += __shfl_xor_sync(0xffffffffu, acc, 1);
            if (lig == 0) {
                float sv = (j < srclen) ? acc : -1e18f;
                sh_p2[iw * SS + j] = make_float2(sv, __int_as_float(e.x));
            }
        }
    }
    __syncthreads();

    // ---- restage value[b] over sh_q, vw table over sh_qw ----
    const float* vb = value + b * SS * HH;
    for (int k = tid * 4; k < SS * HH; k += NT * 4)
        *(float4*)(sh_q + k) = *(const float4*)(vb + k);
    for (int k = tid * 4; k < TBL; k += NT * 4)
        *(float4*)(sh_qw + k) = *(const float4*)(vw_emb + k);

    // ================= Phase B: softmax, pre-normalized (warps 0..7) =========
    if (w < TI) {
        float2 vals[8];
        float m = -3.0e38f;
        #pragma unroll
        for (int k = 0; k < 8; k++) {
            vals[k] = sh_p2[w * SS + lane + k * 32];
            m = fmaxf(m, vals[k].x);
        }
        #pragma unroll
        for (int o = 16; o; o >>= 1) m = fmaxf(m, __shfl_xor_sync(0xffffffffu, m, o));
        float ssum = 0.0f;
        #pragma unroll
        for (int k = 0; k < 8; k++) {
            float e = __expf(vals[k].x - m);   // masked -> 0
            vals[k].x = e;
            ssum += e;
        }
        #pragma unroll
        for (int o = 16; o; o >>= 1) ssum += __shfl_xor_sync(0xffffffffu, ssum, o);
        const float inv = 1.0f / ssum;
        #pragma unroll
        for (int k = 0; k < 8; k++)
            sh_p2[w * SS + lane + k * 32] = make_float2(vals[k].x * inv, vals[k].y);
    }
    __syncthreads();

    // ================= Phase C: output =================
    // thread -> (row ci, j parity jp, float2 h).
    float2* part2 = (float2*)(sm + O_E12);   // overlay (e12 dead)
    {
        const int ci = tid >> 7;              // 0..7
        const int sub = tid & 127;
        const int jp = sub >> 6;              // 0..1 (warp-uniform)
        const int hq = sub & 63;
        const float2* prow = sh_p2 + ci * SS;
        const float* vwb = sh_qw + hq * 2;
        const float* vvb = sh_q  + hq * 2;
        float2 acc = make_float2(0.0f, 0.0f);
        #pragma unroll 4
        for (int j = jp; j < srclen; j += 2) {
            const float2 pe = prow[j];
            const int e1 = __float_as_int(pe.y);
            const float2 vw = *(const float2*)(vwb + e1 * HH);
            const float2 vv = *(const float2*)(vvb + j  * HH);
            acc.x = fmaf(pe.x * vw.x, vv.x, acc.x);
            acc.y = fmaf(pe.x * vw.y, vv.y, acc.y);
        }
        part2[tid] = acc;
    }
    __syncthreads();
    if (tid < 512) {
        const int ci = tid >> 6;
        const int hq = tid & 63;
        const float2 r0 = part2[ci * 128 + hq];
        const float2 r1 = part2[ci * 128 + 64 + hq];
        float2 o = make_float2(r0.x + r1.x, r0.y + r1.y);
        *(float2*)(out + ((size_t)b * SS + i0 + ci) * HH + hq * 2) = o;
    }
}

extern "C" void kernel_launch(void* const* d_in, const int* in_sizes, int n_in,
                              void* d_out, int out_size) {
    const float* query   = (const float*)d_in[0];
    const float* key_t   = (const float*)d_in[1];
    const float* value   = (const float*)d_in[2];
    const float* rel_emb = (const float*)d_in[3];
    const float* qw_emb  = (const float*)d_in[4];
    const float* kw_emb  = (const float*)d_in[5];
    const float* vw_emb  = (const float*)d_in[6];
    const int*   src_len = (const int*)d_in[7];
    const int*   rel_idx = (const int*)d_in[8];
    float* out = (float*)d_out;

    cudaFuncSetAttribute(rgat_kernel,
                         cudaFuncAttributeMaxDynamicSharedMemorySize, SMEM_BYTES);

    rgat_kernel<<<BB * (SS / TI), NT, SMEM_BYTES>>>(
        query, key_t, value, rel_emb, qw_emb, kw_emb, vw_emb,
        src_len, rel_idx, out);
}

// round 8
// speedup vs baseline: 1.1000x; 1.0172x over previous
#include <cuda_runtime.h>

#define BB 4
#define SS 256
#define HH 128
#define NR 40
#define TI 8
#define NT 1024

// shared layout (float words)
#define O_QW   0            // 5120 qw   (phase C: vw)
#define O_KW   5120         // 5120 kw
#define O_REL  10240        // 5120 rel
#define O_Q    15360        // 32768 query[b]  (phase C: value[b])
#define O_E12  48128        // 8*256 int2 (e1, e2)  (phase C: partials overlay)
#define O_P    52224        // 8*256 float2 (a*inv, e1 bits)
#define SMEM_FLOATS 56320
#define SMEM_BYTES  (SMEM_FLOATS * 4)

typedef unsigned long long ull;

__device__ __forceinline__ ull mul2(ull a, ull b) {
    ull d; asm("mul.rn.f32x2 %0, %1, %2;" : "=l"(d) : "l"(a), "l"(b)); return d;
}
__device__ __forceinline__ ull fma2(ull a, ull b, ull c) {
    ull d; asm("fma.rn.f32x2 %0, %1, %2, %3;" : "=l"(d) : "l"(a), "l"(b), "l"(c)); return d;
}
__device__ __forceinline__ ull add2(ull a, ull b) {
    ull d; asm("add.rn.f32x2 %0, %1, %2;" : "=l"(d) : "l"(a), "l"(b)); return d;
}
__device__ __forceinline__ void upk(ull v, float& lo, float& hi) {
    asm("mov.b64 {%0, %1}, %2;" : "=f"(lo), "=f"(hi) : "l"(v));
}
__device__ __forceinline__ ull pk(float lo, float hi) {
    ull r; asm("mov.b64 %0, {%1, %2};" : "=l"(r) : "f"(lo), "f"(hi)); return r;
}
__device__ __forceinline__ float tanhap(float x) {
    float r; asm("tanh.approx.f32 %0, %1;" : "=f"(r) : "f"(x)); return r;
}
// packed tanh: unpack, 2x MUFU.TANH, repack
__device__ __forceinline__ ull tanh2(ull x) {
    float lo, hi; upk(x, lo, hi);
    return pk(tanhap(lo), tanhap(hi));
}

__global__ void __launch_bounds__(NT, 1)
rgat_kernel(const float* __restrict__ query, const float* __restrict__ key,
            const float* __restrict__ value, const float* __restrict__ rel_emb,
            const float* __restrict__ qw_emb, const float* __restrict__ kw_emb,
            const float* __restrict__ vw_emb, const int* __restrict__ src_len,
            const int* __restrict__ rel_idx, float* __restrict__ out)
{
    extern __shared__ float sm[];
    float*  sh_qw  = sm + O_QW;
    float*  sh_kw  = sm + O_KW;
    float*  sh_rel = sm + O_REL;
    float*  sh_q   = sm + O_Q;
    int2*   sh_e12 = (int2*)(sm + O_E12);
    float2* sh_p2  = (float2*)(sm + O_P);

    const int tid = threadIdx.x;
    const int b  = blockIdx.x / (SS / TI);
    const int i0 = (blockIdx.x % (SS / TI)) * TI;
    const int srclen = src_len[b];

    const int TBL = NR * HH; // 5120

    // ---- stage tables ----
    for (int k = tid * 4; k < TBL; k += NT * 4) {
        *(float4*)(sh_qw  + k) = *(const float4*)(qw_emb  + k);
        *(float4*)(sh_kw  + k) = *(const float4*)(kw_emb  + k);
        *(float4*)(sh_rel + k) = *(const float4*)(rel_emb + k);
    }
    // ---- stage full query[b] ----
    const float* qb = query + b * SS * HH;
    for (int k = tid * 4; k < SS * HH; k += NT * 4)
        *(float4*)(sh_q + k) = *(const float4*)(qb + k);

    // ---- stage e12: .x = e1 = rel_idx[b,j,i0+ii] (transpose), .y = e2 = rel_idx[b,i0+ii,j] ----
    if (tid < 512) {
        int j = tid >> 1;
        int c = (tid & 1) * 4;
        int4 v = *(const int4*)(rel_idx + ((size_t)b * SS + j) * SS + i0 + c);
        sh_e12[(c + 0) * SS + j].x = v.x;
        sh_e12[(c + 1) * SS + j].x = v.y;
        sh_e12[(c + 2) * SS + j].x = v.z;
        sh_e12[(c + 3) * SS + j].x = v.w;

        int ii = tid >> 6;
        int j4 = (tid & 63) * 4;
        int4 u = *(const int4*)(rel_idx + ((size_t)b * SS + i0 + ii) * SS + j4);
        sh_e12[ii * SS + j4 + 0].y = u.x;
        sh_e12[ii * SS + j4 + 1].y = u.y;
        sh_e12[ii * SS + j4 + 2].y = u.z;
        sh_e12[ii * SS + j4 + 3].y = u.w;
    }
    __syncthreads();

    const int w    = tid >> 5;
    const int lane = tid & 31;

    // ================= Phase A: scores =================
    // warp -> (row iw = w>>2, j offset p = w&3); four 8-lane groups each own
    // one j; lane covers 16 h (8x packed f32x2 lanes).
    {
        const int iw  = w >> 2;
        const int p   = w & 3;
        const int g   = lane >> 3;
        const int lig = lane & 7;

        const float* kb = key + ((size_t)b * SS + i0 + iw) * HH + lig * 4;
        const ulonglong2 kr0 = *(const ulonglong2*)(kb + 0);
        const ulonglong2 kr1 = *(const ulonglong2*)(kb + 32);
        const ulonglong2 kr2 = *(const ulonglong2*)(kb + 64);
        const ulonglong2 kr3 = *(const ulonglong2*)(kb + 96);

        #pragma unroll 2
        for (int jj = 0; jj < 16; jj++) {
            const int jb = p + (jj << 4);      // warp-uniform
            const int j  = jb + (g << 2);
            if (jb >= srclen) {
                if (lig == 0) sh_p2[iw * SS + j] = make_float2(-1e18f, 0.0f);
                continue;
            }
            const int2 e = sh_e12[iw * SS + j];          // broadcast in group
            const float* qp  = sh_q   + j   * HH + lig * 4;
            const float* qwp = sh_qw  + e.x * HH + lig * 4;
            const float* kwp = sh_kw  + e.y * HH + lig * 4;
            const float* rp  = sh_rel + e.x * HH + lig * 4;

            ull a0 = 0, a1 = 0, a2 = 0, a3 = 0;
#define ASTEP(KR, OFF, ACC) { \
            const ulonglong2 q  = *(const ulonglong2*)(qp  + OFF); \
            const ulonglong2 qw = *(const ulonglong2*)(qwp + OFF); \
            const ulonglong2 kw = *(const ulonglong2*)(kwp + OFF); \
            const ulonglong2 r  = *(const ulonglong2*)(rp  + OFF); \
            ACC = fma2(r.x, tanh2(fma2(qw.x, q.x, mul2(kw.x, KR.x))), ACC); \
            ACC = fma2(r.y, tanh2(fma2(qw.y, q.y, mul2(kw.y, KR.y))), ACC); }
            ASTEP(kr0,  0, a0)
            ASTEP(kr1, 32, a1)
            ASTEP(kr2, 64, a2)
            ASTEP(kr3, 96, a3)
#undef ASTEP
            ull s2 = add2(add2(a0, a1), add2(a2, a3));
            float slo, shi; upk(s2, slo, shi);
            float acc = slo + shi;
            // 8-lane group butterfly (xor offsets stay within the group)
            acc += __shfl_xor_sync(0xffffffffu, acc, 4);
            acc += __shfl_xor_sync(0xffffffffu, acc, 2);
            acc += __shfl_xor_sync(0xffffffffu, acc, 1);
            if (lig == 0) {
                float sv = (j < srclen) ? acc : -1e18f;
                sh_p2[iw * SS + j] = make_float2(sv, __int_as_float(e.x));
            }
        }
    }
    __syncthreads();

    // ---- restage value[b] over sh_q, vw table over sh_qw ----
    const float* vb = value + b * SS * HH;
    for (int k = tid * 4; k < SS * HH; k += NT * 4)
        *(float4*)(sh_q + k) = *(const float4*)(vb + k);
    for (int k = tid * 4; k < TBL; k += NT * 4)
        *(float4*)(sh_qw + k) = *(const float4*)(vw_emb + k);

    // ================= Phase B: softmax, pre-normalized (warps 0..7) =========
    if (w < TI) {
        float2 vals[8];
        float m = -3.0e38f;
        #pragma unroll
        for (int k = 0; k < 8; k++) {
            vals[k] = sh_p2[w * SS + lane + k * 32];
            m = fmaxf(m, vals[k].x);
        }
        #pragma unroll
        for (int o = 16; o; o >>= 1) m = fmaxf(m, __shfl_xor_sync(0xffffffffu, m, o));
        float ssum = 0.0f;
        #pragma unroll
        for (int k = 0; k < 8; k++) {
            float e = __expf(vals[k].x - m);   // masked -> 0
            vals[k].x = e;
            ssum += e;
        }
        #pragma unroll
        for (int o = 16; o; o >>= 1) ssum += __shfl_xor_sync(0xffffffffu, ssum, o);
        const float inv = 1.0f / ssum;
        #pragma unroll
        for (int k = 0; k < 8; k++)
            sh_p2[w * SS + lane + k * 32] = make_float2(vals[k].x * inv, vals[k].y);
    }
    __syncthreads();

    // ================= Phase C: output =================
    // thread -> (row ci, j parity jp, float2 h).
    float2* part2 = (float2*)(sm + O_E12);   // overlay (e12 dead)
    {
        const int ci = tid >> 7;              // 0..7
        const int sub = tid & 127;
        const int jp = sub >> 6;              // 0..1 (warp-uniform)
        const int hq = sub & 63;
        const float2* prow = sh_p2 + ci * SS;
        const float* vwb = sh_qw + hq * 2;
        const float* vvb = sh_q  + hq * 2;
        float2 acc = make_float2(0.0f, 0.0f);
        #pragma unroll 4
        for (int j = jp; j < srclen; j += 2) {
            const float2 pe = prow[j];
            const int e1 = __float_as_int(pe.y);
            const float2 vw = *(const float2*)(vwb + e1 * HH);
            const float2 vv = *(const float2*)(vvb + j  * HH);
            acc.x = fmaf(pe.x * vw.x, vv.x, acc.x);
            acc.y = fmaf(pe.x * vw.y, vv.y, acc.y);
        }
        part2[tid] = acc;
    }
    __syncthreads();
    if (tid < 512) {
        const int ci = tid >> 6;
        const int hq = tid & 63;
        const float2 r0 = part2[ci * 128 + hq];
        const float2 r1 = part2[ci * 128 + 64 + hq];
        float2 o = make_float2(r0.x + r1.x, r0.y + r1.y);
        *(float2*)(out + ((size_t)b * SS + i0 + ci) * HH + hq * 2) = o;
    }
}

extern "C" void kernel_launch(void* const* d_in, const int* in_sizes, int n_in,
                              void* d_out, int out_size) {
    const float* query   = (const float*)d_in[0];
    const float* key_t   = (const float*)d_in[1];
    const float* value   = (const float*)d_in[2];
    const float* rel_emb = (const float*)d_in[3];
    const float* qw_emb  = (const float*)d_in[4];
    const float* kw_emb  = (const float*)d_in[5];
    const float* vw_emb  = (const float*)d_in[6];
    const int*   src_len = (const int*)d_in[7];
    const int*   rel_idx = (const int*)d_in[8];
    float* out = (float*)d_out;

    cudaFuncSetAttribute(rgat_kernel,
                         cudaFuncAttributeMaxDynamicSharedMemorySize, SMEM_BYTES);

    rgat_kernel<<<BB * (SS / TI), NT, SMEM_BYTES>>>(
        query, key_t, value, rel_emb, qw_emb, kw_emb, vw_emb,
        src_len, rel_idx, out);
}

// round 12
// speedup vs baseline: 1.2222x; 1.1111x over previous
#include <cuda_runtime.h>
#include <cuda_fp16.h>

#define BB 4
#define SS 256
#define HH 128
#define NR 40
#define TI 8
#define NT 1024

// ---- shared layout ----
// float-word offsets (phase A, fp32):
#define O_QW   0            // 5120 qw
#define O_KW   5120         // 5120 kw
#define O_REL  10240        // 5120 rel
#define O_Q    15360        // 32768 query[b]
#define O_E12  48128        // int2[2048]  (phase C: float4[1024] partials overlay)
#define O_P    52224        // float2[2048] (a*inv, e1 bits)
#define SMEM_FLOATS 56320
#define SMEM_BYTES  (SMEM_FLOATS * 4)     // 225280
// byte offsets (phase C overlay of the qw..q region):
#define CB_VAL 0            // half[32768] value[b] (64KB)
#define CB_VW  65536        // half[5120]  vw       (10KB)

typedef unsigned long long ull;

__device__ __forceinline__ ull mul2(ull a, ull b) {
    ull d; asm("mul.rn.f32x2 %0, %1, %2;" : "=l"(d) : "l"(a), "l"(b)); return d;
}
__device__ __forceinline__ ull fma2(ull a, ull b, ull c) {
    ull d; asm("fma.rn.f32x2 %0, %1, %2, %3;" : "=l"(d) : "l"(a), "l"(b), "l"(c)); return d;
}
__device__ __forceinline__ ull add2(ull a, ull b) {
    ull d; asm("add.rn.f32x2 %0, %1, %2;" : "=l"(d) : "l"(a), "l"(b)); return d;
}
__device__ __forceinline__ void upk(ull v, float& lo, float& hi) {
    asm("mov.b64 {%0, %1}, %2;" : "=f"(lo), "=f"(hi) : "l"(v));
}
__device__ __forceinline__ ull pk(float lo, float hi) {
    ull r; asm("mov.b64 %0, {%1, %2};" : "=l"(r) : "f"(lo), "f"(hi)); return r;
}
__device__ __forceinline__ float tanhap(float x) {
    float r; asm("tanh.approx.f32 %0, %1;" : "=f"(r) : "f"(x)); return r;
}
__device__ __forceinline__ ull tanh2(ull x) {
    float lo, hi; upk(x, lo, hi);
    return pk(tanhap(lo), tanhap(hi));
}
__device__ __forceinline__ __half2 u2h(unsigned u) { __half2 h; *(unsigned*)&h = u; return h; }
__device__ __forceinline__ unsigned h2u(__half2 h) { return *(unsigned*)&h; }

__global__ void __launch_bounds__(NT, 1)
rgat_kernel(const float* __restrict__ query, const float* __restrict__ key,
            const float* __restrict__ value, const float* __restrict__ rel_emb,
            const float* __restrict__ qw_emb, const float* __restrict__ kw_emb,
            const float* __restrict__ vw_emb, const int* __restrict__ src_len,
            const int* __restrict__ rel_idx, float* __restrict__ out)
{
    extern __shared__ __align__(16) char smc[];
    float*  sm     = (float*)smc;
    float*  sh_qw  = sm + O_QW;
    float*  sh_kw  = sm + O_KW;
    float*  sh_rel = sm + O_REL;
    float*  sh_q   = sm + O_Q;
    int2*   sh_e12 = (int2*)(sm + O_E12);
    float2* sh_p2  = (float2*)(sm + O_P);

    const int tid = threadIdx.x;
    const int b  = blockIdx.x / (SS / TI);
    const int i0 = (blockIdx.x % (SS / TI)) * TI;
    const int srclen = src_len[b];

    const int TBL = NR * HH; // 5120

    // ---- stage tables (fp32) ----
    for (int k = tid * 4; k < TBL; k += NT * 4) {
        *(float4*)(sh_qw  + k) = *(const float4*)(qw_emb  + k);
        *(float4*)(sh_kw  + k) = *(const float4*)(kw_emb  + k);
        *(float4*)(sh_rel + k) = *(const float4*)(rel_emb + k);
    }
    // ---- stage full query[b] (fp32) ----
    const float* qb = query + (size_t)b * SS * HH;
    for (int k = tid * 4; k < SS * HH; k += NT * 4)
        *(float4*)(sh_q + k) = *(const float4*)(qb + k);

    // ---- stage e12: .x = e1 = rel_idx[b,j,i0+ii] (transpose), .y = e2 = rel_idx[b,i0+ii,j] ----
    if (tid < 512) {
        int j = tid >> 1;
        int c = (tid & 1) * 4;
        int4 v = *(const int4*)(rel_idx + ((size_t)b * SS + j) * SS + i0 + c);
        sh_e12[(c + 0) * SS + j].x = v.x;
        sh_e12[(c + 1) * SS + j].x = v.y;
        sh_e12[(c + 2) * SS + j].x = v.z;
        sh_e12[(c + 3) * SS + j].x = v.w;

        int ii = tid >> 6;
        int j4 = (tid & 63) * 4;
        int4 u = *(const int4*)(rel_idx + ((size_t)b * SS + i0 + ii) * SS + j4);
        sh_e12[ii * SS + j4 + 0].y = u.x;
        sh_e12[ii * SS + j4 + 1].y = u.y;
        sh_e12[ii * SS + j4 + 2].y = u.z;
        sh_e12[ii * SS + j4 + 3].y = u.w;
    }
    __syncthreads();

    const int w    = tid >> 5;
    const int lane = tid & 31;

    // ================= Phase A: scores (fp32 f32x2 + MUFU.TANH) =================
    // warp -> (row iw = w>>2, j offset p = w&3); four 8-lane groups each own
    // one j; lane covers 16 h (8x packed f32x2 lanes).
    {
        const int iw  = w >> 2;
        const int p   = w & 3;
        const int g   = lane >> 3;
        const int lig = lane & 7;

        const float* kb = key + ((size_t)b * SS + i0 + iw) * HH + lig * 4;
        const ulonglong2 kr0 = *(const ulonglong2*)(kb + 0);
        const ulonglong2 kr1 = *(const ulonglong2*)(kb + 32);
        const ulonglong2 kr2 = *(const ulonglong2*)(kb + 64);
        const ulonglong2 kr3 = *(const ulonglong2*)(kb + 96);

        #pragma unroll 2
        for (int jj = 0; jj < 16; jj++) {
            const int jb = p + (jj << 4);      // warp-uniform
            const int j  = jb + (g << 2);
            if (jb >= srclen) {
                if (lig == 0) sh_p2[iw * SS + j] = make_float2(-1e18f, 0.0f);
                continue;
            }
            const int2 e = sh_e12[iw * SS + j];          // broadcast in group
            const float* qp  = sh_q   + j   * HH + lig * 4;
            const float* qwp = sh_qw  + e.x * HH + lig * 4;
            const float* kwp = sh_kw  + e.y * HH + lig * 4;
            const float* rp  = sh_rel + e.x * HH + lig * 4;

            ull a0 = 0, a1 = 0, a2 = 0, a3 = 0;
#define ASTEP(KR, OFF, ACC) { \
            const ulonglong2 q  = *(const ulonglong2*)(qp  + OFF); \
            const ulonglong2 qw = *(const ulonglong2*)(qwp + OFF); \
            const ulonglong2 kw = *(const ulonglong2*)(kwp + OFF); \
            const ulonglong2 r  = *(const ulonglong2*)(rp  + OFF); \
            ACC = fma2(r.x, tanh2(fma2(qw.x, q.x, mul2(kw.x, KR.x))), ACC); \
            ACC = fma2(r.y, tanh2(fma2(qw.y, q.y, mul2(kw.y, KR.y))), ACC); }
            ASTEP(kr0,  0, a0)
            ASTEP(kr1, 32, a1)
            ASTEP(kr2, 64, a2)
            ASTEP(kr3, 96, a3)
#undef ASTEP
            ull s2 = add2(add2(a0, a1), add2(a2, a3));
            float slo, shi; upk(s2, slo, shi);
            float acc = slo + shi;
            // 8-lane group butterfly (xor offsets stay within the group)
            acc += __shfl_xor_sync(0xffffffffu, acc, 4);
            acc += __shfl_xor_sync(0xffffffffu, acc, 2);
            acc += __shfl_xor_sync(0xffffffffu, acc, 1);
            if (lig == 0) {
                float sv = (j < srclen) ? acc : -1e18f;
                sh_p2[iw * SS + j] = make_float2(sv, __int_as_float(e.x));
            }
        }
    }
    __syncthreads();

    // ---- restage value[b] and vw as fp16 over the qw/kw/q region ----
    #define CVT8(DSTOFF, SRC, K) { \
        float4 a = *(const float4*)((SRC) + (K)); \
        float4 c = *(const float4*)((SRC) + (K) + 4); \
        uint4 u; \
        u.x = h2u(__floats2half2_rn(a.x, a.y)); \
        u.y = h2u(__floats2half2_rn(a.z, a.w)); \
        u.z = h2u(__floats2half2_rn(c.x, c.y)); \
        u.w = h2u(__floats2half2_rn(c.z, c.w)); \
        *(uint4*)(smc + (DSTOFF) + (K) * 2) = u; }

    const float* vb = value + (size_t)b * SS * HH;
    for (int k = tid * 8; k < SS * HH; k += NT * 8)
        CVT8(CB_VAL, vb, k)
    for (int k = tid * 8; k < NR * HH; k += NT * 8)
        CVT8(CB_VW, vw_emb, k)
    #undef CVT8

    // ================= Phase B: softmax, pre-normalized (warps 0..7) =========
    if (w < TI) {
        float2 vals[8];
        float m = -3.0e38f;
        #pragma unroll
        for (int k = 0; k < 8; k++) {
            vals[k] = sh_p2[w * SS + lane + k * 32];
            m = fmaxf(m, vals[k].x);
        }
        #pragma unroll
        for (int o = 16; o; o >>= 1) m = fmaxf(m, __shfl_xor_sync(0xffffffffu, m, o));
        float ssum = 0.0f;
        #pragma unroll
        for (int k = 0; k < 8; k++) {
            float e = __expf(vals[k].x - m);   // masked -> 0
            vals[k].x = e;
            ssum += e;
        }
        #pragma unroll
        for (int o = 16; o; o >>= 1) ssum += __shfl_xor_sync(0xffffffffu, ssum, o);
        const float inv = 1.0f / ssum;
        #pragma unroll
        for (int k = 0; k < 8; k++)
            sh_p2[w * SS + lane + k * 32] = make_float2(vals[k].x * inv, vals[k].y);
    }
    __syncthreads();

    // ================= Phase C: output (fp16 operands, fp32 accumulate) =====
    // thread -> (row ci, j phase jp 0..3, h-quad hq). warp = (ci, jp) uniform;
    // (a,e1) one broadcast LDS.64; vw/value half4 LDS.64 conflict-free.
    float4* part4 = (float4*)(sm + O_E12);   // overlay (e12 dead), 1024 x float4
    {
        const int ci = tid >> 7;              // 0..7
        const int sub = tid & 127;
        const int jp = sub >> 5;              // 0..3 (warp-uniform)
        const int hq = sub & 31;              // h-quad, h = hq*4
        const float2* prow = sh_p2 + ci * SS;
        const char* vwb = smc + CB_VW  + hq * 8;
        const char* vvb = smc + CB_VAL + hq * 8;
        float4 acc = make_float4(0.0f, 0.0f, 0.0f, 0.0f);
        #pragma unroll 4
        for (int j = jp; j < srclen; j += 4) {
            const float2 pe = prow[j];
            const int e1 = __float_as_int(pe.y);
            const uint2 wu = *(const uint2*)(vwb + e1 * 256);
            const uint2 vu = *(const uint2*)(vvb + j  * 256);
            const float2 f0 = __half22float2(__hmul2(u2h(wu.x), u2h(vu.x)));
            const float2 f1 = __half22float2(__hmul2(u2h(wu.y), u2h(vu.y)));
            acc.x = fmaf(pe.x, f0.x, acc.x);
            acc.y = fmaf(pe.x, f0.y, acc.y);
            acc.z = fmaf(pe.x, f1.x, acc.z);
            acc.w = fmaf(pe.x, f1.y, acc.w);
        }
        part4[tid] = acc;
    }
    __syncthreads();
    if (tid < 256) {
        const int ci = tid >> 5;              // 0..7
        const int hq = tid & 31;
        const float4 r0 = part4[ci * 128 +  0 + hq];
        const float4 r1 = part4[ci * 128 + 32 + hq];
        const float4 r2 = part4[ci * 128 + 64 + hq];
        const float4 r3 = part4[ci * 128 + 96 + hq];
        float4 o;
        o.x = (r0.x + r1.x) + (r2.x + r3.x);
        o.y = (r0.y + r1.y) + (r2.y + r3.y);
        o.z = (r0.z + r1.z) + (r2.z + r3.z);
        o.w = (r0.w + r1.w) + (r2.w + r3.w);
        *(float4*)(out + ((size_t)b * SS + i0 + ci) * HH + hq * 4) = o;
    }
}

extern "C" void kernel_launch(void* const* d_in, const int* in_sizes, int n_in,
                              void* d_out, int out_size) {
    const float* query   = (const float*)d_in[0];
    const float* key_t   = (const float*)d_in[1];
    const float* value   = (const float*)d_in[2];
    const float* rel_emb = (const float*)d_in[3];
    const float* qw_emb  = (const float*)d_in[4];
    const float* kw_emb  = (const float*)d_in[5];
    const float* vw_emb  = (const float*)d_in[6];
    const int*   src_len = (const int*)d_in[7];
    const int*   rel_idx = (const int*)d_in[8];
    float* out = (float*)d_out;

    cudaFuncSetAttribute(rgat_kernel,
                         cudaFuncAttributeMaxDynamicSharedMemorySize, SMEM_BYTES);

    rgat_kernel<<<BB * (SS / TI), NT, SMEM_BYTES>>>(
        query, key_t, value, rel_emb, qw_emb, kw_emb, vw_emb,
        src_len, rel_idx, out);
}